// round 16
// baseline (speedup 1.0000x reference)
#include <cuda_runtime.h>
#include <cuda_bf16.h>
#include <cstdint>

// BilateralFilter (SqueezeSeg): out[b,z,a,k,c] = exp(-||x[b,z,a]-nbr_k||^2 / (2*theta_c^2))
// B=16, Z=64, A=512, K=14 (3x5 minus center), theta=[.015,.015,.01,.01]
// -> per (pixel,k) output float4 = (e1,e1,e2,e2), only 2 distinct exps.
//
// R16: R6 base (AoS float4 tile, TA=256/896thr/occ2/ZC=8, 1 barrier/z-step,
// __stcs, __expf) with the row feed converted to cp.async (LDGSTS):
// 780 lanes copy one 4B (pixel,component) slice of row z+2 straight to smem
// with native zero-fill (src_size 0) at borders; commit_group + wait_group 1
// gives a full z-step of latency hiding. No register prefetch, no STS.
// 8-slot circular buffer: write slot is always 4 rows from any read slot.

#define BB 16
#define ZZ 64
#define AA 512
#define KK 14

#define TA 256                // pixels (a) per CTA
#define NT 896                // threads
#define PT 4                  // outputs per thread per z-step
#define HW (TA + 4)           // 260 halo width
#define ZC 8                  // z-rows per CTA

__global__ __launch_bounds__(NT, 2)
void bilateral_kernel(const float* __restrict__ x, float4* __restrict__ out)
{
    __shared__ float4 tile[8][HW];   // circular rows, slot = gz & 7 (33,280 B)

    const int tid = threadIdx.x;
    const int a0 = blockIdx.x * TA;
    const int z0 = blockIdx.y * ZC;
    const int b  = blockIdx.z;

    const uint32_t smem_base = (uint32_t)__cvta_generic_to_shared(&tile[0][0]);

    // ---- cp.async lane mapping: t < 780 -> (pixel, comp) slice ----
    const int pix  = tid / 3;             // 0..259 (and beyond for tid>=780)
    const int comp = tid - pix * 3;       // 0..2
    const bool cp_lane = (tid < 3 * HW);
    const int ga = a0 + pix - 2;
    const bool a_ok = cp_lane && (ga >= 0) && (ga < AA);
    // per-row global addr for (gz): x + ((b*ZZ+gz)*AA + ga)*3 + comp
    const float* gsrc0 = x + ((size_t)b * ZZ * AA + ga) * 3 + comp;
    const uint32_t sm_off = (uint32_t)(pix * 16 + comp * 4);

    // ---- prologue: rows z0-1, z0, z0+1 via cp.async ----
    if (cp_lane) {
        #pragma unroll
        for (int r = 0; r < 3; ++r) {
            const int gz = z0 + r - 1;
            const int ok = (a_ok && gz >= 0 && gz < ZZ) ? 4 : 0;
            const uint32_t sa = smem_base + (uint32_t)((gz & 7) * HW * 16) + sm_off;
            const float* gp = gsrc0 + (size_t)gz * AA * 3;
            asm volatile("cp.async.ca.shared.global [%0], [%1], 4, %2;"
                         :: "r"(sa), "l"(gp), "r"(ok));
        }
    }
    asm volatile("cp.async.commit_group;");
    asm volatile("cp.async.wait_group 0;");

    // ---- decode once: k, (i,j) invariant for this thread ----
    const int p0 = tid / KK;          // 0..63
    const int k  = tid - p0 * KK;     // 0..13
    const int kk = k + (k >= 7);      // skip center (flat 7)
    const int i  = kk / 5;            // 0..2
    const int j  = kk - i * 5;        // 0..4

    const float C1 = -1.0f / (2.0f * 0.015f * 0.015f);
    const float C2 = -1.0f / (2.0f * 0.01f  * 0.01f );

    float4* ob = out + ((size_t)((b * ZZ + z0) * AA + a0)) * KK + tid;

    #pragma unroll 1
    for (int z = z0; z < z0 + ZC; ++z) {
        // ---- issue cp.async for row z+2 (landed by step z+1's wait) ----
        {
            const int gz = z + 2;
            if (cp_lane && gz <= z0 + ZC) {
                const int ok = (a_ok && gz < ZZ) ? 4 : 0;
                const uint32_t sa = smem_base + (uint32_t)((gz & 7) * HW * 16) + sm_off;
                const float* gp = gsrc0 + (size_t)gz * AA * 3;
                asm volatile("cp.async.ca.shared.global [%0], [%1], 4, %2;"
                             :: "r"(sa), "l"(gp), "r"(ok));
            }
        }
        asm volatile("cp.async.commit_group;");
        asm volatile("cp.async.wait_group 1;");   // row z+1 (prev group) done
        __syncthreads();                          // visible to all threads

        // ---- compute row z (reads slots (z-1..z+1)&7) ----
        const int sc = z & 7;
        const int sn = (z - 1 + i) & 7;
        #pragma unroll
        for (int it = 0; it < PT; ++it) {
            const int p = p0 + it * 64;
            const float4 c4 = tile[sc][p + 2];
            const float4 n4 = tile[sn][p + j];
            const float dx = c4.x - n4.x;
            const float dy = c4.y - n4.y;
            const float dz = c4.z - n4.z;
            const float d2 = fmaf(dz, dz, fmaf(dy, dy, dx * dx));
            const float e1 = __expf(d2 * C1);
            const float e2 = __expf(d2 * C2);
            __stcs(&ob[it * NT], make_float4(e1, e1, e2, e2));
        }

        ob += (size_t)AA * KK;
    }
}

extern "C" void kernel_launch(void* const* d_in, const int* in_sizes, int n_in,
                              void* d_out, int out_size)
{
    (void)in_sizes; (void)n_in; (void)out_size;
    const float* x = (const float*)d_in[0];
    float4* out = (float4*)d_out;

    dim3 grid(AA / TA, ZZ / ZC, BB);   // 2 x 8 x 16 = 256 CTAs
    dim3 block(NT);                    // 896 threads
    bilateral_kernel<<<grid, block>>>(x, out);
}